// round 5
// baseline (speedup 1.0000x reference)
#include <cuda_runtime.h>
#include <cstdint>

// SparseLinearV: y = scatter(W_coo) @ x + bias
// Round 5: tcgen05 is unusable (harness PTX target is plain sm_103 — no 'a'
// suffix features). Optimize the legacy mma.sync tf32 path instead:
//  - pre-round both operands to tf32 (rna) in preprocessing -> no cvt in loop
//  - k-interleave permutation baked into gmem -> fragment loads are LDS.64
//  - x transposed to K-major (g_XT) so B fragments are LDS.64 too
//  - 128x256 CTA tile, BK=32, 64x64 warp tiles, cp.async double buffer

#define IN_F   4096
#define OUT_F  4096
#define NCOLS  4096

__device__ float g_W [(size_t)IN_F * OUT_F];   // W (M x K) row-major, k-permuted tf32
__device__ float g_XT[(size_t)NCOLS * OUT_F];  // x^T (N x K) row-major, k-permuted tf32

// ---------------------------------------------------------------------------
// helpers
// ---------------------------------------------------------------------------
__device__ __forceinline__ float rna_tf32(float x) {
    unsigned u;
    asm("cvt.rna.tf32.f32 %0, %1;" : "=r"(u) : "f"(x));
    return __uint_as_float(u);
}
__device__ __forceinline__ void cp_async16(uint32_t smem_dst, const void* gsrc) {
    asm volatile("cp.async.cg.shared.global [%0], [%1], 16;" :: "r"(smem_dst), "l"(gsrc));
}
__device__ __forceinline__ void cp_commit() { asm volatile("cp.async.commit_group;"); }
template<int N> __device__ __forceinline__ void cp_wait() {
    asm volatile("cp.async.wait_group %0;" :: "n"(N) : "memory");
}
__device__ __forceinline__ uint32_t smem_u32(const void* p) {
    uint32_t a;
    asm("{ .reg .u64 t; cvta.to.shared.u64 t, %1; cvt.u32.u64 %0, t; }" : "=r"(a) : "l"(p));
    return a;
}
__device__ __forceinline__ void mma_tf32(float c[4], const unsigned a[4], const unsigned b[2]) {
    asm volatile(
        "mma.sync.aligned.m16n8k8.row.col.f32.tf32.tf32.f32 "
        "{%0,%1,%2,%3}, {%4,%5,%6,%7}, {%8,%9}, {%0,%1,%2,%3};"
        : "+f"(c[0]), "+f"(c[1]), "+f"(c[2]), "+f"(c[3])
        : "r"(a[0]), "r"(a[1]), "r"(a[2]), "r"(a[3]), "r"(b[0]), "r"(b[1]));
}

// ---------------------------------------------------------------------------
// Preprocessing
// ---------------------------------------------------------------------------
__global__ void zero_W_kernel() {
    size_t n4 = (size_t)IN_F * OUT_F / 4;
    float4 z = make_float4(0.f, 0.f, 0.f, 0.f);
    float4* p = reinterpret_cast<float4*>(g_W);
    for (size_t i = (size_t)blockIdx.x * blockDim.x + threadIdx.x;
         i < n4; i += (size_t)gridDim.x * blockDim.x)
        p[i] = z;
}

__global__ void scatter_kernel(const int* __restrict__ rows, const int* __restrict__ cols,
                               const float* __restrict__ vals, int nnz) {
    int i = blockIdx.x * blockDim.x + threadIdx.x;
    if (i < nnz) atomicAdd(&g_W[(size_t)rows[i] * OUT_F + cols[i]], vals[i]);
}

// Round W to tf32 (rna) AND permute each 8-group of k in place:
//  src (k0..k7) -> dst (k0,k4,k1,k5,k2,k6,k3,k7)
// so fragment pair (c, c+4) becomes adjacent (2c, 2c+1).
__global__ void round_perm_W_kernel() {
    size_t n8 = (size_t)IN_F * OUT_F / 8;
    float4* p = reinterpret_cast<float4*>(g_W);
    for (size_t i = (size_t)blockIdx.x * blockDim.x + threadIdx.x;
         i < n8; i += (size_t)gridDim.x * blockDim.x) {
        float4 lo = p[2 * i];       // k0..k3
        float4 hi = p[2 * i + 1];   // k4..k7
        float4 d0 = make_float4(rna_tf32(lo.x), rna_tf32(hi.x),
                                rna_tf32(lo.y), rna_tf32(hi.y));
        float4 d1 = make_float4(rna_tf32(lo.z), rna_tf32(hi.z),
                                rna_tf32(lo.w), rna_tf32(hi.w));
        p[2 * i]     = d0;
        p[2 * i + 1] = d1;
    }
}

// x (K x N) row-major -> g_XT (N x K) row-major, tf32-rounded, k-permuted.
__global__ void transpose_round_perm_kernel(const float* __restrict__ x) {
    __shared__ float t[32][33];
    int bx = blockIdx.x * 32;  // n base
    int by = blockIdx.y * 32;  // k base
    int tx = threadIdx.x, ty = threadIdx.y;
#pragma unroll
    for (int i = 0; i < 4; i++)
        t[ty + 8 * i][tx] = x[(size_t)(by + ty + 8 * i) * NCOLS + bx + tx];
    __syncthreads();
    // permuted destination k within this thread's 8-group
    const int kk = tx & 7;
    const int kp = (tx & ~7) + ((kk < 4) ? (2 * kk) : (2 * (kk - 4) + 1));
#pragma unroll
    for (int i = 0; i < 4; i++)
        g_XT[(size_t)(bx + ty + 8 * i) * OUT_F + by + kp] = rna_tf32(t[tx][ty + 8 * i]);
}

// ---------------------------------------------------------------------------
// GEMM: C(4096x4096) = W @ x + bias   (A = g_W, B = g_XT both K-major tf32)
//   BM=128, BN=256, BK=32, 256 threads, warp tile 64x64, double buffer.
// ---------------------------------------------------------------------------
#define BM 128
#define BN 256
#define BK 32
#define NT (OUT_F / BK)        // 128
#define AST 40                 // A smem row stride in floats (32 data + 8 pad)
#define BST 40                 // B smem row stride in floats
#define TILE_A_FLOATS (BM * AST)   // 5120 floats = 20480 B
#define TILE_B_FLOATS (BN * BST)   // 10240 floats = 40960 B
#define STAGE_FLOATS (TILE_A_FLOATS + TILE_B_FLOATS)
#define SMEM_TOTAL (2 * STAGE_FLOATS * 4)

__global__ __launch_bounds__(256, 1)
void gemm_tf32_kernel(const float* __restrict__ bias, float* __restrict__ C) {
    extern __shared__ float smem[];
    float* As[2] = { smem, smem + STAGE_FLOATS };
    float* Bs[2] = { smem + TILE_A_FLOATS, smem + STAGE_FLOATS + TILE_A_FLOATS };

    const int tid  = threadIdx.x;
    const int lane = tid & 31;
    const int wid  = tid >> 5;
    const int wm   = wid >> 2;        // 0..1  (M direction, 64 rows)
    const int wn   = wid & 3;         // 0..3  (N direction, 64 cols)
    const int r    = lane >> 2;       // 0..7
    const int c2   = (lane & 3) * 2;  // permuted k-pair offset (and epi col pair)

    const int rowBase = blockIdx.y * BM;
    const int colBase = blockIdx.x * BN;

    const uint32_t sA[2] = { smem_u32(As[0]), smem_u32(As[1]) };
    const uint32_t sB[2] = { smem_u32(Bs[0]), smem_u32(Bs[1]) };

    // Loader mapping: each 16B chunk covers 4 permuted-k floats.
    // A: 128 rows x 8 chunks = 1024 chunks, threads take tid + 256*l, l=0..3
    // B: 256 rows x 8 chunks = 2048 chunks, threads take tid + 256*l, l=0..7
    auto load_stage = [&](int s, int k0) {
#pragma unroll
        for (int l = 0; l < 4; l++) {
            const int ch  = tid + 256 * l;
            const int row = ch >> 3;
            const int c16 = ch & 7;
            cp_async16(sA[s] + (uint32_t)(row * AST + c16 * 4) * 4,
                       &g_W[(size_t)(rowBase + row) * OUT_F + k0 + c16 * 4]);
        }
#pragma unroll
        for (int l = 0; l < 8; l++) {
            const int ch  = tid + 256 * l;
            const int row = ch >> 3;
            const int c16 = ch & 7;
            cp_async16(sB[s] + (uint32_t)(row * BST + c16 * 4) * 4,
                       &g_XT[(size_t)(colBase + row) * OUT_F + k0 + c16 * 4]);
        }
        cp_commit();
    };

    float acc[4][8][4];
#pragma unroll
    for (int i = 0; i < 4; i++)
#pragma unroll
        for (int j = 0; j < 8; j++)
#pragma unroll
            for (int q = 0; q < 4; q++) acc[i][j][q] = 0.f;

    load_stage(0, 0);

    for (int t = 0; t < NT; t++) {
        const int cur = t & 1;
        if (t + 1 < NT) load_stage(cur ^ 1, (t + 1) * BK);
        cp_wait<1>();
        __syncthreads();

        const float* Ab = As[cur];
        const float* Bb = Bs[cur];
#pragma unroll
        for (int ks = 0; ks < 4; ks++) {
            const int kb = ks * 8 + c2;   // permuted word offset: (c, c+4) pair
            unsigned afr[4][4], bfr[8][2];
#pragma unroll
            for (int i = 0; i < 4; i++) {
                const int m = wm * 64 + i * 16 + r;
                float2 p0 = *reinterpret_cast<const float2*>(&Ab[m * AST + kb]);
                float2 p1 = *reinterpret_cast<const float2*>(&Ab[(m + 8) * AST + kb]);
                afr[i][0] = __float_as_uint(p0.x);  // A[m][c]
                afr[i][1] = __float_as_uint(p1.x);  // A[m+8][c]
                afr[i][2] = __float_as_uint(p0.y);  // A[m][c+4]
                afr[i][3] = __float_as_uint(p1.y);  // A[m+8][c+4]
            }
#pragma unroll
            for (int j = 0; j < 8; j++) {
                const int n = wn * 64 + j * 8 + r;
                float2 q = *reinterpret_cast<const float2*>(&Bb[n * BST + kb]);
                bfr[j][0] = __float_as_uint(q.x);   // B[c][n]
                bfr[j][1] = __float_as_uint(q.y);   // B[c+4][n]
            }
#pragma unroll
            for (int i = 0; i < 4; i++)
#pragma unroll
                for (int j = 0; j < 8; j++)
                    mma_tf32(acc[i][j], afr[i], bfr[j]);
        }
        __syncthreads();
    }

    // Epilogue: bias add + float2 stores.
#pragma unroll
    for (int i = 0; i < 4; i++) {
        const int row0 = rowBase + wm * 64 + i * 16 + r;
#pragma unroll
        for (int j = 0; j < 8; j++) {
            const int col = colBase + wn * 64 + j * 8 + c2;
            float2 bv = *reinterpret_cast<const float2*>(&bias[col]);
            float2 o0 = make_float2(acc[i][j][0] + bv.x, acc[i][j][1] + bv.y);
            float2 o1 = make_float2(acc[i][j][2] + bv.x, acc[i][j][3] + bv.y);
            *reinterpret_cast<float2*>(&C[(size_t)row0 * NCOLS + col])       = o0;
            *reinterpret_cast<float2*>(&C[(size_t)(row0 + 8) * NCOLS + col]) = o1;
        }
    }
}

// ---------------------------------------------------------------------------
// Launch
// ---------------------------------------------------------------------------
extern "C" void kernel_launch(void* const* d_in, const int* in_sizes, int n_in,
                              void* d_out, int out_size) {
    const float* x    = (const float*)d_in[0];
    const int*   rows = (const int*)d_in[1];
    const int*   cols = (const int*)d_in[2];
    const float* vals = (const float*)d_in[3];
    const float* bias = (const float*)d_in[4];
    float*       y    = (float*)d_out;
    const int nnz = in_sizes[1];

    cudaFuncSetAttribute(gemm_tf32_kernel,
                         cudaFuncAttributeMaxDynamicSharedMemorySize, SMEM_TOTAL);

    zero_W_kernel<<<1184, 256>>>();
    scatter_kernel<<<(nnz + 255) / 256, 256>>>(rows, cols, vals, nnz);
    round_perm_W_kernel<<<1184, 256>>>();
    transpose_round_perm_kernel<<<dim3(NCOLS / 32, OUT_F / 32), dim3(32, 8)>>>(x);

    dim3 grid(NCOLS / BN, IN_F / BM);  // 16 x 32 = 512 CTAs
    gemm_tf32_kernel<<<grid, 256, SMEM_TOTAL>>>(bias, y);
}

// round 8
// speedup vs baseline: 1.0577x; 1.0577x over previous
#include <cuda_runtime.h>
#include <cstdint>

// SparseLinearV: y = scatter(W_coo) @ x + bias
// Round 8: resubmit of R6/R7 (neither ran — GPU acquisition timeouts, infra).
// R5 post-mortem: regression came from occupancy dropping to 1 CTA/SM
// (128x256 tile, 122 KB smem) — barrier/drain latency exposed. Keep R5's
// wins (pre-rounded tf32 operands, k-interleave permutation -> LDS.64
// fragment loads, no cvt in loop) but restore 2 CTAs/SM with a 128x128
// tile, BK=32, 64x32 warp tiles, 80 KB smem/CTA double buffer.

#define IN_F   4096
#define OUT_F  4096
#define NCOLS  4096

__device__ float g_W [(size_t)IN_F * OUT_F];   // W (M x K) row-major, k-permuted tf32
__device__ float g_XT[(size_t)NCOLS * OUT_F];  // x^T (N x K) row-major, k-permuted tf32

// ---------------------------------------------------------------------------
// helpers
// ---------------------------------------------------------------------------
__device__ __forceinline__ float rna_tf32(float x) {
    unsigned u;
    asm("cvt.rna.tf32.f32 %0, %1;" : "=r"(u) : "f"(x));
    return __uint_as_float(u);
}
__device__ __forceinline__ void cp_async16(uint32_t smem_dst, const void* gsrc) {
    asm volatile("cp.async.cg.shared.global [%0], [%1], 16;" :: "r"(smem_dst), "l"(gsrc));
}
__device__ __forceinline__ void cp_commit() { asm volatile("cp.async.commit_group;"); }
template<int N> __device__ __forceinline__ void cp_wait() {
    asm volatile("cp.async.wait_group %0;" :: "n"(N) : "memory");
}
__device__ __forceinline__ uint32_t smem_u32(const void* p) {
    uint32_t a;
    asm("{ .reg .u64 t; cvta.to.shared.u64 t, %1; cvt.u32.u64 %0, t; }" : "=r"(a) : "l"(p));
    return a;
}
__device__ __forceinline__ void mma_tf32(float c[4], const unsigned a[4], const unsigned b[2]) {
    asm volatile(
        "mma.sync.aligned.m16n8k8.row.col.f32.tf32.tf32.f32 "
        "{%0,%1,%2,%3}, {%4,%5,%6,%7}, {%8,%9}, {%0,%1,%2,%3};"
        : "+f"(c[0]), "+f"(c[1]), "+f"(c[2]), "+f"(c[3])
        : "r"(a[0]), "r"(a[1]), "r"(a[2]), "r"(a[3]), "r"(b[0]), "r"(b[1]));
}

// ---------------------------------------------------------------------------
// Preprocessing
// ---------------------------------------------------------------------------
__global__ void zero_W_kernel() {
    size_t n4 = (size_t)IN_F * OUT_F / 4;
    float4 z = make_float4(0.f, 0.f, 0.f, 0.f);
    float4* p = reinterpret_cast<float4*>(g_W);
    for (size_t i = (size_t)blockIdx.x * blockDim.x + threadIdx.x;
         i < n4; i += (size_t)gridDim.x * blockDim.x)
        p[i] = z;
}

__global__ void scatter_kernel(const int* __restrict__ rows, const int* __restrict__ cols,
                               const float* __restrict__ vals, int nnz) {
    int i = blockIdx.x * blockDim.x + threadIdx.x;
    if (i < nnz) atomicAdd(&g_W[(size_t)rows[i] * OUT_F + cols[i]], vals[i]);
}

// Round W to tf32 (rna) AND permute each 8-group of k in place:
//  src (k0..k7) -> dst (k0,k4,k1,k5,k2,k6,k3,k7)
// so fragment pair (c, c+4) becomes adjacent (2c, 2c+1).
__global__ void round_perm_W_kernel() {
    size_t n8 = (size_t)IN_F * OUT_F / 8;
    float4* p = reinterpret_cast<float4*>(g_W);
    for (size_t i = (size_t)blockIdx.x * blockDim.x + threadIdx.x;
         i < n8; i += (size_t)gridDim.x * blockDim.x) {
        float4 lo = p[2 * i];       // k0..k3
        float4 hi = p[2 * i + 1];   // k4..k7
        float4 d0 = make_float4(rna_tf32(lo.x), rna_tf32(hi.x),
                                rna_tf32(lo.y), rna_tf32(hi.y));
        float4 d1 = make_float4(rna_tf32(lo.z), rna_tf32(hi.z),
                                rna_tf32(lo.w), rna_tf32(hi.w));
        p[2 * i]     = d0;
        p[2 * i + 1] = d1;
    }
}

// x (K x N) row-major -> g_XT (N x K) row-major, tf32-rounded, k-permuted.
__global__ void transpose_round_perm_kernel(const float* __restrict__ x) {
    __shared__ float t[32][33];
    int bx = blockIdx.x * 32;  // n base
    int by = blockIdx.y * 32;  // k base
    int tx = threadIdx.x, ty = threadIdx.y;
#pragma unroll
    for (int i = 0; i < 4; i++)
        t[ty + 8 * i][tx] = x[(size_t)(by + ty + 8 * i) * NCOLS + bx + tx];
    __syncthreads();
    const int kk = tx & 7;
    const int kp = (tx & ~7) + ((kk < 4) ? (2 * kk) : (2 * (kk - 4) + 1));
#pragma unroll
    for (int i = 0; i < 4; i++)
        g_XT[(size_t)(bx + ty + 8 * i) * OUT_F + by + kp] = rna_tf32(t[tx][ty + 8 * i]);
}

// ---------------------------------------------------------------------------
// GEMM: C(4096x4096) = W @ x + bias   (A = g_W, B = g_XT both K-major tf32)
//   BM=128, BN=128, BK=32, 256 threads, warp tile 64x32, double buffer,
//   2 CTAs/SM (80 KB smem/CTA, <=128 regs).
// ---------------------------------------------------------------------------
#define BM 128
#define BN 128
#define BK 32
#define NT (OUT_F / BK)        // 128
#define AST 40                 // A smem row stride in floats (32 data + 8 pad)
#define BST 40                 // B smem row stride in floats
#define TILE_A_FLOATS (BM * AST)   // 5120 floats = 20480 B
#define TILE_B_FLOATS (BN * BST)   // 5120 floats = 20480 B
#define STAGE_FLOATS (TILE_A_FLOATS + TILE_B_FLOATS)
#define SMEM_TOTAL (2 * STAGE_FLOATS * 4)    // 81920 B

__global__ __launch_bounds__(256, 2)
void gemm_tf32_kernel(const float* __restrict__ bias, float* __restrict__ C) {
    extern __shared__ float smem[];
    float* As[2] = { smem, smem + STAGE_FLOATS };
    float* Bs[2] = { smem + TILE_A_FLOATS, smem + STAGE_FLOATS + TILE_A_FLOATS };

    const int tid  = threadIdx.x;
    const int lane = tid & 31;
    const int wid  = tid >> 5;
    const int wm   = wid & 1;         // 0..1  (M direction, 64 rows)
    const int wn   = wid >> 1;        // 0..3  (N direction, 32 cols)
    const int r    = lane >> 2;       // 0..7
    const int c2   = (lane & 3) * 2;  // permuted k-pair offset (and epi col pair)

    const int rowBase = blockIdx.y * BM;
    const int colBase = blockIdx.x * BN;

    const uint32_t sA[2] = { smem_u32(As[0]), smem_u32(As[1]) };
    const uint32_t sB[2] = { smem_u32(Bs[0]), smem_u32(Bs[1]) };

    // Loader mapping: 16B chunk = 4 permuted-k floats.
    // A: 128 rows x 8 chunks = 1024 chunks; B likewise. 4 chunks/thread each.
    auto load_stage = [&](int s, int k0) {
#pragma unroll
        for (int l = 0; l < 4; l++) {
            const int ch  = tid + 256 * l;
            const int row = ch >> 3;
            const int c16 = ch & 7;
            cp_async16(sA[s] + (uint32_t)(row * AST + c16 * 4) * 4,
                       &g_W[(size_t)(rowBase + row) * OUT_F + k0 + c16 * 4]);
        }
#pragma unroll
        for (int l = 0; l < 4; l++) {
            const int ch  = tid + 256 * l;
            const int row = ch >> 3;
            const int c16 = ch & 7;
            cp_async16(sB[s] + (uint32_t)(row * BST + c16 * 4) * 4,
                       &g_XT[(size_t)(colBase + row) * OUT_F + k0 + c16 * 4]);
        }
        cp_commit();
    };

    float acc[4][4][4];
#pragma unroll
    for (int i = 0; i < 4; i++)
#pragma unroll
        for (int j = 0; j < 4; j++)
#pragma unroll
            for (int q = 0; q < 4; q++) acc[i][j][q] = 0.f;

    load_stage(0, 0);

    for (int t = 0; t < NT; t++) {
        const int cur = t & 1;
        if (t + 1 < NT) load_stage(cur ^ 1, (t + 1) * BK);
        cp_wait<1>();
        __syncthreads();

        const float* Ab = As[cur];
        const float* Bb = Bs[cur];
#pragma unroll
        for (int ks = 0; ks < 4; ks++) {
            const int kb = ks * 8 + c2;   // permuted word offset: (c, c+4) pair
            unsigned afr[4][4], bfr[4][2];
#pragma unroll
            for (int i = 0; i < 4; i++) {
                const int m = wm * 64 + i * 16 + r;
                float2 p0 = *reinterpret_cast<const float2*>(&Ab[m * AST + kb]);
                float2 p1 = *reinterpret_cast<const float2*>(&Ab[(m + 8) * AST + kb]);
                afr[i][0] = __float_as_uint(p0.x);  // A[m][c]
                afr[i][1] = __float_as_uint(p1.x);  // A[m+8][c]
                afr[i][2] = __float_as_uint(p0.y);  // A[m][c+4]
                afr[i][3] = __float_as_uint(p1.y);  // A[m+8][c+4]
            }
#pragma unroll
            for (int j = 0; j < 4; j++) {
                const int n = wn * 32 + j * 8 + r;
                float2 q = *reinterpret_cast<const float2*>(&Bb[n * BST + kb]);
                bfr[j][0] = __float_as_uint(q.x);   // B[c][n]
                bfr[j][1] = __float_as_uint(q.y);   // B[c+4][n]
            }
#pragma unroll
            for (int i = 0; i < 4; i++)
#pragma unroll
                for (int j = 0; j < 4; j++)
                    mma_tf32(acc[i][j], afr[i], bfr[j]);
        }
        __syncthreads();
    }

    // Epilogue: bias add + float2 stores.
#pragma unroll
    for (int i = 0; i < 4; i++) {
        const int row0 = rowBase + wm * 64 + i * 16 + r;
#pragma unroll
        for (int j = 0; j < 4; j++) {
            const int col = colBase + wn * 32 + j * 8 + c2;
            float2 bv = *reinterpret_cast<const float2*>(&bias[col]);
            float2 o0 = make_float2(acc[i][j][0] + bv.x, acc[i][j][1] + bv.y);
            float2 o1 = make_float2(acc[i][j][2] + bv.x, acc[i][j][3] + bv.y);
            *reinterpret_cast<float2*>(&C[(size_t)row0 * NCOLS + col])       = o0;
            *reinterpret_cast<float2*>(&C[(size_t)(row0 + 8) * NCOLS + col]) = o1;
        }
    }
}

// ---------------------------------------------------------------------------
// Launch
// ---------------------------------------------------------------------------
extern "C" void kernel_launch(void* const* d_in, const int* in_sizes, int n_in,
                              void* d_out, int out_size) {
    const float* x    = (const float*)d_in[0];
    const int*   rows = (const int*)d_in[1];
    const int*   cols = (const int*)d_in[2];
    const float* vals = (const float*)d_in[3];
    const float* bias = (const float*)d_in[4];
    float*       y    = (float*)d_out;
    const int nnz = in_sizes[1];

    cudaFuncSetAttribute(gemm_tf32_kernel,
                         cudaFuncAttributeMaxDynamicSharedMemorySize, SMEM_TOTAL);

    zero_W_kernel<<<1184, 256>>>();
    scatter_kernel<<<(nnz + 255) / 256, 256>>>(rows, cols, vals, nnz);
    round_perm_W_kernel<<<1184, 256>>>();
    transpose_round_perm_kernel<<<dim3(NCOLS / 32, OUT_F / 32), dim3(32, 8)>>>(x);

    dim3 grid(NCOLS / BN, IN_F / BM);  // 32 x 32 = 1024 CTAs
    gemm_tf32_kernel<<<grid, 256, SMEM_TOTAL>>>(bias, y);
}

// round 11
// speedup vs baseline: 1.8777x; 1.7752x over previous
#include <cuda_runtime.h>
#include <cuda_fp16.h>
#include <cstdint>

// SparseLinearV: y = scatter(W_coo) @ x + bias
// Round 11: resubmit of R9/R10 (neither ran — GPU acquisition timeouts).
// R8 post-mortem — R2 (854us, 3.0 aux/MMA) vs R8 (889us, 0.75 aux/MMA) at
// equal occupancy proves the legacy tf32 mma pipe itself is saturated
// (~330 MACs/SM/cyc). Swap the engine: m16n8k16.f16 does 2x the MACs per
// instruction, and fp16's 10-bit mantissa == tf32's mantissa, so precision
// is unchanged (values are O(1-10), fp32 accumulate).
// Keep R8's 128x128 / BK=32 / 2 CTAs-per-SM skeleton; operands become fp16
// with a per-16-group k-permutation (0,1,8,9, 2,3,10,11, 4,5,12,13,
// 6,7,14,15) so every fragment load is one LDS.64.

#define IN_F   4096
#define OUT_F  4096
#define NCOLS  4096

__device__ float  g_W  [(size_t)IN_F * OUT_F];   // densify scratch (fp32 atomics)
__device__ __half g_Wh [(size_t)IN_F * OUT_F];   // W (M x K), k-permuted fp16
__device__ __half g_XTh[(size_t)NCOLS * OUT_F];  // x^T (N x K), k-permuted fp16

// ---------------------------------------------------------------------------
// helpers
// ---------------------------------------------------------------------------
__device__ __forceinline__ void cp_async16(uint32_t smem_dst, const void* gsrc) {
    asm volatile("cp.async.cg.shared.global [%0], [%1], 16;" :: "r"(smem_dst), "l"(gsrc));
}
__device__ __forceinline__ void cp_commit() { asm volatile("cp.async.commit_group;"); }
template<int N> __device__ __forceinline__ void cp_wait() {
    asm volatile("cp.async.wait_group %0;" :: "n"(N) : "memory");
}
__device__ __forceinline__ uint32_t smem_u32(const void* p) {
    uint32_t a;
    asm("{ .reg .u64 t; cvta.to.shared.u64 t, %1; cvt.u32.u64 %0, t; }" : "=r"(a) : "l"(p));
    return a;
}
__device__ __forceinline__ void mma_f16(float c[4], const unsigned a[4], const unsigned b[2]) {
    asm volatile(
        "mma.sync.aligned.m16n8k16.row.col.f32.f16.f16.f32 "
        "{%0,%1,%2,%3}, {%4,%5,%6,%7}, {%8,%9}, {%0,%1,%2,%3};"
        : "+f"(c[0]), "+f"(c[1]), "+f"(c[2]), "+f"(c[3])
        : "r"(a[0]), "r"(a[1]), "r"(a[2]), "r"(a[3]), "r"(b[0]), "r"(b[1]));
}
__device__ __forceinline__ uint32_t h2u(__half2 h) {
    return *reinterpret_cast<uint32_t*>(&h);
}

// ---------------------------------------------------------------------------
// Preprocessing
// ---------------------------------------------------------------------------
__global__ void zero_W_kernel() {
    size_t n4 = (size_t)IN_F * OUT_F / 4;
    float4 z = make_float4(0.f, 0.f, 0.f, 0.f);
    float4* p = reinterpret_cast<float4*>(g_W);
    for (size_t i = (size_t)blockIdx.x * blockDim.x + threadIdx.x;
         i < n4; i += (size_t)gridDim.x * blockDim.x)
        p[i] = z;
}

__global__ void scatter_kernel(const int* __restrict__ rows, const int* __restrict__ cols,
                               const float* __restrict__ vals, int nnz) {
    int i = blockIdx.x * blockDim.x + threadIdx.x;
    if (i < nnz) atomicAdd(&g_W[(size_t)rows[i] * OUT_F + cols[i]], vals[i]);
}

// Convert W fp32 -> fp16 with per-16-group permutation:
//  dst order = src (0,1,8,9, 2,3,10,11, 4,5,12,13, 6,7,14,15)
__global__ void convert_perm_W_kernel() {
    size_t ng = (size_t)IN_F * OUT_F / 16;
    for (size_t g = (size_t)blockIdx.x * blockDim.x + threadIdx.x;
         g < ng; g += (size_t)gridDim.x * blockDim.x) {
        const float4* src = reinterpret_cast<const float4*>(g_W) + g * 4;
        float4 a = src[0];  // k0..3
        float4 b = src[1];  // k4..7
        float4 c = src[2];  // k8..11
        float4 d = src[3];  // k12..15
        uint4 lo, hi;
        lo.x = h2u(__floats2half2_rn(a.x, a.y));  // 0,1
        lo.y = h2u(__floats2half2_rn(c.x, c.y));  // 8,9
        lo.z = h2u(__floats2half2_rn(a.z, a.w));  // 2,3
        lo.w = h2u(__floats2half2_rn(c.z, c.w));  // 10,11
        hi.x = h2u(__floats2half2_rn(b.x, b.y));  // 4,5
        hi.y = h2u(__floats2half2_rn(d.x, d.y));  // 12,13
        hi.z = h2u(__floats2half2_rn(b.z, b.w));  // 6,7
        hi.w = h2u(__floats2half2_rn(d.z, d.w));  // 14,15
        uint4* dst = reinterpret_cast<uint4*>(g_Wh) + g * 2;
        dst[0] = lo;
        dst[1] = hi;
    }
}

// x (K x N) fp32 row-major -> g_XTh (N x K) fp16 row-major, k-permuted.
__global__ void transpose_convert_perm_kernel(const float* __restrict__ x) {
    __shared__ float t[32][33];   // t[k_local][n_local]
    const int bx = blockIdx.x * 32;  // n base
    const int by = blockIdx.y * 32;  // k base
    const int tx = threadIdx.x, ty = threadIdx.y;
#pragma unroll
    for (int i = 0; i < 4; i++)
        t[ty + 8 * i][tx] = x[(size_t)(by + ty + 8 * i) * NCOLS + bx + tx];
    __syncthreads();
    // Each thread writes one permuted quad (4 halves = 8 B).
    const int qc = tx & 7;             // quad 0..7 within 32 k
    const int nl = (tx >> 3) * 8 + ty; // 0..31
    const int grp = qc >> 2;           // 16-group 0..1
    const int q4  = qc & 3;            // quad within group
    const int s0 = grp * 16 + 2 * q4;  // src k of first pair
    const int s2 = s0 + 8;             // src k of second pair
    uint2 out;
    out.x = h2u(__floats2half2_rn(t[s0][nl], t[s0 + 1][nl]));
    out.y = h2u(__floats2half2_rn(t[s2][nl], t[s2 + 1][nl]));
    *reinterpret_cast<uint2*>(&g_XTh[(size_t)(bx + nl) * OUT_F + by + grp * 16 + q4 * 4]) = out;
}

// ---------------------------------------------------------------------------
// GEMM: C(4096x4096) = W @ x + bias  (A = g_Wh, B = g_XTh, both K-major fp16)
//   BM=128, BN=128, BK=32, 256 threads, warp tile 64x32, double buffer.
//   smem row stride 48 halves (24 words): r*24 mod 32 in {0,24,16,8} ->
//   conflict-free LDS.64 half-warp phases.
// ---------------------------------------------------------------------------
#define BM 128
#define BN 128
#define BK 32
#define NT (OUT_F / BK)            // 128
#define AST 48                     // halves per smem row (32 data + 16 pad)
#define TILE_HALVES (BM * AST)     // 6144 halves = 12288 B
#define STAGE_HALVES (2 * TILE_HALVES)
#define SMEM_TOTAL (2 * STAGE_HALVES * 2)   // 49152 B

__global__ __launch_bounds__(256, 2)
void gemm_f16_kernel(const float* __restrict__ bias, float* __restrict__ C) {
    extern __shared__ __align__(16) __half smem[];
    __half* As[2] = { smem, smem + STAGE_HALVES };
    __half* Bs[2] = { smem + TILE_HALVES, smem + STAGE_HALVES + TILE_HALVES };

    const int tid  = threadIdx.x;
    const int lane = tid & 31;
    const int wid  = tid >> 5;
    const int wm   = wid & 1;         // 0..1  (M direction, 64 rows)
    const int wn   = wid >> 1;        // 0..3  (N direction, 32 cols)
    const int r    = lane >> 2;       // 0..7
    const int c    = lane & 3;        // 0..3
    const int c2   = c * 2;           // epilogue col pair

    const int rowBase = blockIdx.y * BM;
    const int colBase = blockIdx.x * BN;

    const uint32_t sA[2] = { smem_u32(As[0]), smem_u32(As[1]) };
    const uint32_t sB[2] = { smem_u32(Bs[0]), smem_u32(Bs[1]) };

    // Loader: 16B chunk = 8 halves. A tile: 128 rows x 4 chunks = 512 chunks,
    // 2 per thread; B likewise.
    auto load_stage = [&](int s, int k0) {
#pragma unroll
        for (int l = 0; l < 2; l++) {
            const int ch  = tid + 256 * l;
            const int row = ch >> 2;
            const int c16 = ch & 3;
            cp_async16(sA[s] + (uint32_t)(row * AST + c16 * 8) * 2,
                       &g_Wh[(size_t)(rowBase + row) * OUT_F + k0 + c16 * 8]);
        }
#pragma unroll
        for (int l = 0; l < 2; l++) {
            const int ch  = tid + 256 * l;
            const int row = ch >> 2;
            const int c16 = ch & 3;
            cp_async16(sB[s] + (uint32_t)(row * AST + c16 * 8) * 2,
                       &g_XTh[(size_t)(colBase + row) * OUT_F + k0 + c16 * 8]);
        }
        cp_commit();
    };

    float acc[4][4][4];
#pragma unroll
    for (int i = 0; i < 4; i++)
#pragma unroll
        for (int j = 0; j < 4; j++)
#pragma unroll
            for (int q = 0; q < 4; q++) acc[i][j][q] = 0.f;

    load_stage(0, 0);

    for (int t = 0; t < NT; t++) {
        const int cur = t & 1;
        if (t + 1 < NT) load_stage(cur ^ 1, (t + 1) * BK);
        cp_wait<1>();
        __syncthreads();

        const __half* Ab = As[cur];
        const __half* Bb = Bs[cur];
#pragma unroll
        for (int ks = 0; ks < 2; ks++) {
            // permuted quad for this thread: halves (2c,2c+1,2c+8,2c+9) at
            // position ks*16 + c*4
            const int kh = ks * 16 + c * 4;
            unsigned afr[4][4], bfr[4][2];
#pragma unroll
            for (int i = 0; i < 4; i++) {
                const int m = wm * 64 + i * 16 + r;
                uint2 p0 = *reinterpret_cast<const uint2*>(&Ab[m * AST + kh]);
                uint2 p1 = *reinterpret_cast<const uint2*>(&Ab[(m + 8) * AST + kh]);
                afr[i][0] = p0.x;   // (r,   2c),(r,   2c+1)
                afr[i][1] = p1.x;   // (r+8, 2c),(r+8, 2c+1)
                afr[i][2] = p0.y;   // (r,   2c+8),(r,   2c+9)
                afr[i][3] = p1.y;   // (r+8, 2c+8),(r+8, 2c+9)
            }
#pragma unroll
            for (int j = 0; j < 4; j++) {
                const int n = wn * 32 + j * 8 + r;
                uint2 q = *reinterpret_cast<const uint2*>(&Bb[n * AST + kh]);
                bfr[j][0] = q.x;    // (2c,   n),(2c+1, n)
                bfr[j][1] = q.y;    // (2c+8, n),(2c+9, n)
            }
#pragma unroll
            for (int i = 0; i < 4; i++)
#pragma unroll
                for (int j = 0; j < 4; j++)
                    mma_f16(acc[i][j], afr[i], bfr[j]);
        }
        __syncthreads();
    }

    // Epilogue: bias add + float2 stores (D layout same as m16n8k8).
#pragma unroll
    for (int i = 0; i < 4; i++) {
        const int row0 = rowBase + wm * 64 + i * 16 + r;
#pragma unroll
        for (int j = 0; j < 4; j++) {
            const int col = colBase + wn * 32 + j * 8 + c2;
            float2 bv = *reinterpret_cast<const float2*>(&bias[col]);
            float2 o0 = make_float2(acc[i][j][0] + bv.x, acc[i][j][1] + bv.y);
            float2 o1 = make_float2(acc[i][j][2] + bv.x, acc[i][j][3] + bv.y);
            *reinterpret_cast<float2*>(&C[(size_t)row0 * NCOLS + col])       = o0;
            *reinterpret_cast<float2*>(&C[(size_t)(row0 + 8) * NCOLS + col]) = o1;
        }
    }
}

// ---------------------------------------------------------------------------
// Launch
// ---------------------------------------------------------------------------
extern "C" void kernel_launch(void* const* d_in, const int* in_sizes, int n_in,
                              void* d_out, int out_size) {
    const float* x    = (const float*)d_in[0];
    const int*   rows = (const int*)d_in[1];
    const int*   cols = (const int*)d_in[2];
    const float* vals = (const float*)d_in[3];
    const float* bias = (const float*)d_in[4];
    float*       y    = (float*)d_out;
    const int nnz = in_sizes[1];

    cudaFuncSetAttribute(gemm_f16_kernel,
                         cudaFuncAttributeMaxDynamicSharedMemorySize, SMEM_TOTAL);

    zero_W_kernel<<<1184, 256>>>();
    scatter_kernel<<<(nnz + 255) / 256, 256>>>(rows, cols, vals, nnz);
    convert_perm_W_kernel<<<1184, 256>>>();
    transpose_convert_perm_kernel<<<dim3(NCOLS / 32, OUT_F / 32), dim3(32, 8)>>>(x);

    dim3 grid(NCOLS / BN, IN_F / BM);  // 32 x 32 = 1024 CTAs
    gemm_f16_kernel<<<grid, 256, SMEM_TOTAL>>>(bias, y);
}